// round 15
// baseline (speedup 1.0000x reference)
#include <cuda_runtime.h>
#include <cuda_fp16.h>
#include <math.h>
#include <stdint.h>

#define KCODES 512
#define CDIM   64
#define NPIX   131072
#define HW     4096
#define CHW    262144
#define TILE_M 256
#define NT     (NPIX/TILE_M)    // 512 tiles
#define GRID   148              // persistent, 1 CTA/SM
#define THREADS 384             // 8 consumer warps + 4 producer warps
#define NCONS  256
#define CBP    72               // fp16 row pad (144B, conflict-free ldmatrix)
#define CAP    16
#define MARGIN_DOT 2e-3f        // dot-space margin (== 4e-3 in distance space)

// ---------------- smem layout (171008 B, 1 CTA/SM) ----------------
#define OFF_B    0                 // 512*72*2 = 73728
#define OFF_A0   73728             // 256*72*2 = 36864
#define OFF_A1   110592            // 36864
#define OFF_CC   147456            // 2048
#define OFF_IV   149504            // 2048
#define OFF_RINV 151552            // 2*256*4 = 2048
#define OFF_LIST 153600            // 256*16*4 = 16384
#define OFF_CNT  169984            // 1024
#define SM_TOTAL 171008

// ---------------- helpers ----------------
__device__ __forceinline__ uint32_t smem_u32(const void* p) {
    uint32_t a;
    asm("{ .reg .u64 t; cvta.to.shared.u64 t, %1; cvt.u32.u64 %0, t; }" : "=r"(a) : "l"(p));
    return a;
}
__device__ __forceinline__ void ldsm4(uint32_t* r, uint32_t addr) {
    asm volatile("ldmatrix.sync.aligned.m8n8.x4.shared.b16 {%0,%1,%2,%3}, [%4];"
                 : "=r"(r[0]), "=r"(r[1]), "=r"(r[2]), "=r"(r[3]) : "r"(addr));
}
__device__ __forceinline__ void mma16816(float* c, const uint32_t* a,
                                         uint32_t b0, uint32_t b1) {
    asm volatile("mma.sync.aligned.m16n8k16.row.col.f32.f16.f16.f32 "
                 "{%0,%1,%2,%3}, {%4,%5,%6,%7}, {%8,%9}, {%0,%1,%2,%3};"
                 : "+f"(c[0]), "+f"(c[1]), "+f"(c[2]), "+f"(c[3])
                 : "r"(a[0]), "r"(a[1]), "r"(a[2]), "r"(a[3]), "r"(b0), "r"(b1));
}
#define BARALL()  asm volatile("bar.sync 1, 384;" ::: "memory")

// ---------------------------------------------------------------------------
// Warp-specialized persistent kernel. Prune = argmax-dot (codebook rows are
// unit-norm, so cc=1 +/- 5e-7: margin absorbs it). cn==1 rows skip rescore.
// ---------------------------------------------------------------------------
__global__ void __launch_bounds__(THREADS, 1)
vq_kernel(const float* __restrict__ x, const float* __restrict__ cb,
          float* __restrict__ out, int write_idx) {
    extern __shared__ char sm[];
    __half* Bh = (__half*)(sm + OFF_B);
    float*  CC = (float*)(sm + OFF_CC);
    float*  IV = (float*)(sm + OFF_IV);
    float*  RV = (float*)(sm + OFF_RINV);   // per-row x inv norm, 2 buffers
    int*  LIST = (int*)(sm + OFF_LIST);
    int*   CNT = (int*)(sm + OFF_CNT);

    int tid = threadIdx.x, lane = tid & 31, wid = tid >> 5;
    uint32_t smb = smem_u32(sm);
    uint32_t BhB = smb + OFF_B;
    uint32_t Aoff[2] = { smb + OFF_A0, smb + OFF_A1 };
    __half* Aptr[2] = { (__half*)(sm + OFF_A0), (__half*)(sm + OFF_A1) };

    // ---- init (all 384 threads): normalize codebook -> smem fp16 B + CC + IV
    for (int k = tid; k < KCODES; k += THREADS) {
        const float4* r4 = (const float4*)(cb + (size_t)k*CDIM);
        float4 buf[16];
        float ss = 0.f;
        #pragma unroll
        for (int q = 0; q < 16; ++q) {
            buf[q] = r4[q];
            ss += buf[q].x*buf[q].x; ss += buf[q].y*buf[q].y;
            ss += buf[q].z*buf[q].z; ss += buf[q].w*buf[q].w;
        }
        float inv = 1.0f / fmaxf(sqrtf(ss), 1e-12f);
        float cc = 0.f;
        #pragma unroll
        for (int q = 0; q < 16; ++q) {
            float v0 = buf[q].x*inv, v1 = buf[q].y*inv;
            float v2 = buf[q].z*inv, v3 = buf[q].w*inv;
            cc += v0*v0; cc += v1*v1; cc += v2*v2; cc += v3*v3;
            *(__half2*)(Bh + k*CBP + q*4)     = __floats2half2_rn(v0, v1);
            *(__half2*)(Bh + k*CBP + q*4 + 2) = __floats2half2_rn(v2, v3);
        }
        CC[k] = cc;
        IV[k] = inv;
    }
    __syncthreads();

    bool producer = (tid >= NCONS);
    int cur = 0;

    // ---- prologue: producers fill A[0] for first tile ----
    if (producer) {
        int pid = tid - NCONS;
        #pragma unroll
        for (int rep = 0; rep < 2; ++rep) {
            int r = pid + rep*128;
            int n = blockIdx.x*TILE_M + r;
            const float* xb = x + (size_t)(n >> 12)*CHW + (n & 4095);
            float v[CDIM];
            float ss = 0.f;
            #pragma unroll
            for (int c = 0; c < CDIM; ++c) { v[c] = xb[(size_t)c*HW]; ss += v[c]*v[c]; }
            float inv = 1.0f / fmaxf(sqrtf(ss), 1e-12f);
            #pragma unroll
            for (int i = 0; i < 32; ++i)
                *(__half2*)(Aptr[0] + r*CBP + 2*i) =
                    __floats2half2_rn(v[2*i]*inv, v[2*i+1]*inv);
            RV[r] = inv;   // buffer 0
        }
    }
    BARALL();   // A[0] ready

    for (int tile = blockIdx.x; tile < NT; tile += GRID) {
        if (producer) {
            int nxt = tile + GRID;
            if (nxt < NT) {
                int pid = tid - NCONS;
                int nb = cur ^ 1;
                #pragma unroll
                for (int rep = 0; rep < 2; ++rep) {
                    int r = pid + rep*128;
                    int n = nxt*TILE_M + r;
                    const float* xb = x + (size_t)(n >> 12)*CHW + (n & 4095);
                    float v[CDIM];
                    float ss = 0.f;
                    #pragma unroll
                    for (int c = 0; c < CDIM; ++c) { v[c] = xb[(size_t)c*HW]; ss += v[c]*v[c]; }
                    float inv = 1.0f / fmaxf(sqrtf(ss), 1e-12f);
                    #pragma unroll
                    for (int i = 0; i < 32; ++i)
                        *(__half2*)(Aptr[nb] + r*CBP + 2*i) =
                            __floats2half2_rn(v[2*i]*inv, v[2*i+1]*inv);
                    RV[nb*256 + r] = inv;
                }
            }
            BARALL();   // rendezvous: consumers finished tile
        } else {
            // ---- consumers: fully warp-local within the tile ----
            int r0 = wid * 32;
            CNT[r0 + lane] = 0;         // warp-private rows
            __syncwarp();

            // GEMM prune on A[cur]: argmax of raw dot, row-level SHFL maxes
            {
                uint32_t AhB = Aoff[cur];
                uint32_t a[2][4][4];
                {
                    int rsel = lane & 15, kh = (lane >> 4) << 3;
                    #pragma unroll
                    for (int rt = 0; rt < 2; ++rt)
                        #pragma unroll
                        for (int j = 0; j < 4; ++j) {
                            uint32_t ad = AhB + (uint32_t)(((r0 + rt*16 + rsel)*CBP + 16*j + kh) * 2);
                            ldsm4(a[rt][j], ad);
                        }
                }
                int noff = (lane & 7) + ((lane >> 4) << 3);
                int kadd = ((lane >> 3) & 1) << 3;
                int rsub = lane >> 2;
                float best_lo[2] = {-1e30f, -1e30f}, best_hi[2] = {-1e30f, -1e30f};

                for (int chunk = 0; chunk < 8; ++chunk) {
                    float C[2][8][4];
                    #pragma unroll
                    for (int rt = 0; rt < 2; ++rt)
                        #pragma unroll
                        for (int t = 0; t < 8; ++t)
                            { C[rt][t][0]=0.f; C[rt][t][1]=0.f; C[rt][t][2]=0.f; C[rt][t][3]=0.f; }

                    #pragma unroll
                    for (int j = 0; j < 4; ++j) {
                        #pragma unroll
                        for (int tp = 0; tp < 4; ++tp) {
                            int n0 = chunk*64 + tp*16;
                            uint32_t bad = BhB + (uint32_t)(((n0 + noff)*CBP + 16*j + kadd) * 2);
                            uint32_t b[4];
                            ldsm4(b, bad);
                            #pragma unroll
                            for (int rt = 0; rt < 2; ++rt) {
                                mma16816(C[rt][2*tp],   a[rt][j], b[0], b[1]);
                                mma16816(C[rt][2*tp+1], a[rt][j], b[2], b[3]);
                            }
                        }
                    }

                    int code0base = chunk*64 + 2*(lane & 3);
                    #pragma unroll
                    for (int rt = 0; rt < 2; ++rt) {
                        #pragma unroll
                        for (int t = 0; t < 8; ++t) {
                            best_lo[rt] = fmaxf(best_lo[rt], fmaxf(C[rt][t][0], C[rt][t][1]));
                            best_hi[rt] = fmaxf(best_hi[rt], fmaxf(C[rt][t][2], C[rt][t][3]));
                        }
                        best_lo[rt] = fmaxf(best_lo[rt], __shfl_xor_sync(0xffffffffu, best_lo[rt], 1));
                        best_lo[rt] = fmaxf(best_lo[rt], __shfl_xor_sync(0xffffffffu, best_lo[rt], 2));
                        best_hi[rt] = fmaxf(best_hi[rt], __shfl_xor_sync(0xffffffffu, best_hi[rt], 1));
                        best_hi[rt] = fmaxf(best_hi[rt], __shfl_xor_sync(0xffffffffu, best_hi[rt], 2));
                        float thr_lo = best_lo[rt] - MARGIN_DOT, thr_hi = best_hi[rt] - MARGIN_DOT;
                        int row_lo = r0 + rt*16 + rsub, row_hi = row_lo + 8;

                        #pragma unroll
                        for (int t = 0; t < 8; ++t) {
                            int c0 = code0base + t*8;
                            if (C[rt][t][0] >= thr_lo) { int p = atomicAdd(&CNT[row_lo], 1); if (p < CAP) LIST[row_lo*CAP + p] = c0;   }
                            if (C[rt][t][1] >= thr_lo) { int p = atomicAdd(&CNT[row_lo], 1); if (p < CAP) LIST[row_lo*CAP + p] = c0+1; }
                            if (C[rt][t][2] >= thr_hi) { int p = atomicAdd(&CNT[row_hi], 1); if (p < CAP) LIST[row_hi*CAP + p] = c0;   }
                            if (C[rt][t][3] >= thr_hi) { int p = atomicAdd(&CNT[row_hi], 1); if (p < CAP) LIST[row_hi*CAP + p] = c0+1; }
                        }
                    }
                }
            }
            __syncwarp();   // warp's own LIST/CNT visible to its lanes

            // ---- exact fp32 rescore (warp-private: lane = row offset) ----
            {
                int r = r0 + lane;
                int n = tile*TILE_M + r;
                int cn = CNT[r];
                int bk;

                if (cn == 1) {
                    // candidate set provably contains the argmin; 1 element = answer
                    bk = LIST[r*CAP];
                } else {
                    bool ovf = (cn > CAP) || (cn == 0);
                    if (cn > CAP) cn = CAP;

                    float invx = RV[cur*256 + r];
                    const float* xb = x + (size_t)(n >> 12)*CHW + (n & 4095);
                    float v[CDIM];
                    #pragma unroll
                    for (int c = 0; c < CDIM; ++c) v[c] = xb[(size_t)c*HW] * invx;

                    float bd = 1e30f;
                    bk = 0x7fffffff;

                    if (!ovf) {
                        for (int i = 0; i < cn; ++i) {
                            int k = LIST[r*CAP + i];
                            float invk = IV[k];
                            const float4* cb4 = (const float4*)(cb + (size_t)k*CDIM);
                            float d0 = 0.f, d1 = 0.f;
                            #pragma unroll
                            for (int q = 0; q < 16; q += 2) {
                                float4 ca = cb4[q], cb2 = cb4[q+1];
                                d0 = fmaf(v[4*q+0], ca.x*invk, d0);
                                d0 = fmaf(v[4*q+1], ca.y*invk, d0);
                                d0 = fmaf(v[4*q+2], ca.z*invk, d0);
                                d0 = fmaf(v[4*q+3], ca.w*invk, d0);
                                d1 = fmaf(v[4*q+4], cb2.x*invk, d1);
                                d1 = fmaf(v[4*q+5], cb2.y*invk, d1);
                                d1 = fmaf(v[4*q+6], cb2.z*invk, d1);
                                d1 = fmaf(v[4*q+7], cb2.w*invk, d1);
                            }
                            float d = fmaf(-2.f, d0 + d1, CC[k]);
                            if (d < bd || (d == bd && k < bk)) { bd = d; bk = k; }
                        }
                    } else {
                        for (int k = 0; k < KCODES; ++k) {
                            float invk = IV[k];
                            const float4* cb4 = (const float4*)(cb + (size_t)k*CDIM);
                            float d0 = 0.f;
                            #pragma unroll
                            for (int q = 0; q < 16; ++q) {
                                float4 ca = cb4[q];
                                d0 = fmaf(v[4*q+0], ca.x*invk, d0);
                                d0 = fmaf(v[4*q+1], ca.y*invk, d0);
                                d0 = fmaf(v[4*q+2], ca.z*invk, d0);
                                d0 = fmaf(v[4*q+3], ca.w*invk, d0);
                            }
                            float d = fmaf(-2.f, d0, CC[k]);
                            if (d < bd) { bd = d; bk = k; }   // ascending k: first-min
                        }
                    }
                }

                float invk = IV[bk];
                float* ob = out + (size_t)(n >> 12)*CHW + (n & 4095);
                const float4* cbb = (const float4*)(cb + (size_t)bk*CDIM);
                #pragma unroll
                for (int q = 0; q < 16; ++q) {
                    float4 vv = cbb[q];
                    int c = q * 4;
                    ob[(size_t)(c+0)*HW] = vv.x * invk;
                    ob[(size_t)(c+1)*HW] = vv.y * invk;
                    ob[(size_t)(c+2)*HW] = vv.z * invk;
                    ob[(size_t)(c+3)*HW] = vv.w * invk;
                }
                if (write_idx)
                    out[(size_t)NPIX*CDIM + n] = (float)bk;
            }
            BARALL();   // tile fully done; release A[cur] for refill
        }
        cur ^= 1;
    }
}

// ---------------------------------------------------------------------------
extern "C" void kernel_launch(void* const* d_in, const int* in_sizes, int n_in,
                              void* d_out, int out_size) {
    const float* x;
    const float* cb;
    if (in_sizes[0] == KCODES*CDIM) {
        cb = (const float*)d_in[0];
        x  = (const float*)d_in[1];
    } else {
        x  = (const float*)d_in[0];
        cb = (const float*)d_in[1];
    }
    float* out = (float*)d_out;

    cudaFuncSetAttribute(vq_kernel, cudaFuncAttributeMaxDynamicSharedMemorySize, SM_TOTAL);
    int write_idx = (out_size >= NPIX*CDIM + NPIX) ? 1 : 0;
    vq_kernel<<<GRID, THREADS, SM_TOTAL>>>(x, cb, out, write_idx);
}

// round 16
// speedup vs baseline: 1.5019x; 1.5019x over previous
#include <cuda_runtime.h>
#include <cuda_fp16.h>
#include <math.h>
#include <stdint.h>

#define KCODES 512
#define CDIM   64
#define NPIX   131072
#define HW     4096
#define CHW    262144
#define TILE_M 256
#define NT     (NPIX/TILE_M)    // 512 tiles
#define GRID   148              // persistent, 1 CTA/SM
#define THREADS 384             // 8 consumer warps + 4 producer warps
#define NCONS  256
#define CBP    72               // fp16 row pad (144B, conflict-free ldmatrix)
#define CAP    16
#define MARGIN 4e-3f

// ---------------- smem layout (171008 B, 1 CTA/SM) ----------------
#define OFF_B    0                 // 512*72*2 = 73728
#define OFF_A0   73728             // 256*72*2 = 36864
#define OFF_A1   110592            // 36864
#define OFF_CC   147456            // 2048
#define OFF_IV   149504            // 2048
#define OFF_RINV 151552            // 2*256*4 = 2048
#define OFF_LIST 153600            // 256*16*4 = 16384
#define OFF_CNT  169984            // 1024
#define SM_TOTAL 171008

// ---------------- helpers ----------------
__device__ __forceinline__ uint32_t smem_u32(const void* p) {
    uint32_t a;
    asm("{ .reg .u64 t; cvta.to.shared.u64 t, %1; cvt.u32.u64 %0, t; }" : "=r"(a) : "l"(p));
    return a;
}
__device__ __forceinline__ void ldsm4(uint32_t* r, uint32_t addr) {
    asm volatile("ldmatrix.sync.aligned.m8n8.x4.shared.b16 {%0,%1,%2,%3}, [%4];"
                 : "=r"(r[0]), "=r"(r[1]), "=r"(r[2]), "=r"(r[3]) : "r"(addr));
}
__device__ __forceinline__ void mma16816(float* c, const uint32_t* a,
                                         uint32_t b0, uint32_t b1) {
    asm volatile("mma.sync.aligned.m16n8k16.row.col.f32.f16.f16.f32 "
                 "{%0,%1,%2,%3}, {%4,%5,%6,%7}, {%8,%9}, {%0,%1,%2,%3};"
                 : "+f"(c[0]), "+f"(c[1]), "+f"(c[2]), "+f"(c[3])
                 : "r"(a[0]), "r"(a[1]), "r"(a[2]), "r"(a[3]), "r"(b0), "r"(b1));
}
#define BARALL()  asm volatile("bar.sync 1, 384;" ::: "memory")

// ---------------------------------------------------------------------------
// Warp-specialized persistent kernel — exact R14 structure (distance-based
// prune, row-level SHFL thresholds) + cn==1 rescore shortcut (the candidate
// set provably contains the argmin, so a singleton IS the answer).
// ---------------------------------------------------------------------------
__global__ void __launch_bounds__(THREADS, 1)
vq_kernel(const float* __restrict__ x, const float* __restrict__ cb,
          float* __restrict__ out, int write_idx) {
    extern __shared__ char sm[];
    __half* Bh = (__half*)(sm + OFF_B);
    float*  CC = (float*)(sm + OFF_CC);
    float*  IV = (float*)(sm + OFF_IV);
    float*  RV = (float*)(sm + OFF_RINV);   // per-row x inv norm, 2 buffers
    int*  LIST = (int*)(sm + OFF_LIST);
    int*   CNT = (int*)(sm + OFF_CNT);

    int tid = threadIdx.x, lane = tid & 31, wid = tid >> 5;
    uint32_t smb = smem_u32(sm);
    uint32_t BhB = smb + OFF_B;
    uint32_t Aoff[2] = { smb + OFF_A0, smb + OFF_A1 };
    __half* Aptr[2] = { (__half*)(sm + OFF_A0), (__half*)(sm + OFF_A1) };

    // ---- init (all 384 threads): normalize codebook -> smem fp16 B + CC + IV
    for (int k = tid; k < KCODES; k += THREADS) {
        const float4* r4 = (const float4*)(cb + (size_t)k*CDIM);
        float4 buf[16];
        float ss = 0.f;
        #pragma unroll
        for (int q = 0; q < 16; ++q) {
            buf[q] = r4[q];
            ss += buf[q].x*buf[q].x; ss += buf[q].y*buf[q].y;
            ss += buf[q].z*buf[q].z; ss += buf[q].w*buf[q].w;
        }
        float inv = 1.0f / fmaxf(sqrtf(ss), 1e-12f);
        float cc = 0.f;
        #pragma unroll
        for (int q = 0; q < 16; ++q) {
            float v0 = buf[q].x*inv, v1 = buf[q].y*inv;
            float v2 = buf[q].z*inv, v3 = buf[q].w*inv;
            cc += v0*v0; cc += v1*v1; cc += v2*v2; cc += v3*v3;
            *(__half2*)(Bh + k*CBP + q*4)     = __floats2half2_rn(v0, v1);
            *(__half2*)(Bh + k*CBP + q*4 + 2) = __floats2half2_rn(v2, v3);
        }
        CC[k] = cc;
        IV[k] = inv;
    }
    __syncthreads();

    bool producer = (tid >= NCONS);
    int cur = 0;

    // ---- prologue: producers fill A[0] for first tile ----
    if (producer) {
        int pid = tid - NCONS;
        #pragma unroll
        for (int rep = 0; rep < 2; ++rep) {
            int r = pid + rep*128;
            int n = blockIdx.x*TILE_M + r;
            const float* xb = x + (size_t)(n >> 12)*CHW + (n & 4095);
            float v[CDIM];
            float ss = 0.f;
            #pragma unroll
            for (int c = 0; c < CDIM; ++c) { v[c] = xb[(size_t)c*HW]; ss += v[c]*v[c]; }
            float inv = 1.0f / fmaxf(sqrtf(ss), 1e-12f);
            #pragma unroll
            for (int i = 0; i < 32; ++i)
                *(__half2*)(Aptr[0] + r*CBP + 2*i) =
                    __floats2half2_rn(v[2*i]*inv, v[2*i+1]*inv);
            RV[r] = inv;   // buffer 0
        }
    }
    BARALL();   // A[0] ready

    for (int tile = blockIdx.x; tile < NT; tile += GRID) {
        if (producer) {
            int nxt = tile + GRID;
            if (nxt < NT) {
                int pid = tid - NCONS;
                int nb = cur ^ 1;
                #pragma unroll
                for (int rep = 0; rep < 2; ++rep) {
                    int r = pid + rep*128;
                    int n = nxt*TILE_M + r;
                    const float* xb = x + (size_t)(n >> 12)*CHW + (n & 4095);
                    float v[CDIM];
                    float ss = 0.f;
                    #pragma unroll
                    for (int c = 0; c < CDIM; ++c) { v[c] = xb[(size_t)c*HW]; ss += v[c]*v[c]; }
                    float inv = 1.0f / fmaxf(sqrtf(ss), 1e-12f);
                    #pragma unroll
                    for (int i = 0; i < 32; ++i)
                        *(__half2*)(Aptr[nb] + r*CBP + 2*i) =
                            __floats2half2_rn(v[2*i]*inv, v[2*i+1]*inv);
                    RV[nb*256 + r] = inv;
                }
            }
            BARALL();   // rendezvous: consumers finished tile
        } else {
            // ---- consumers: fully warp-local within the tile ----
            int r0 = wid * 32;
            CNT[r0 + lane] = 0;         // warp-private rows
            __syncwarp();

            // GEMM prune on A[cur] (32 rows/warp, row-level SHFL thresholds)
            {
                uint32_t AhB = Aoff[cur];
                uint32_t a[2][4][4];
                {
                    int rsel = lane & 15, kh = (lane >> 4) << 3;
                    #pragma unroll
                    for (int rt = 0; rt < 2; ++rt)
                        #pragma unroll
                        for (int j = 0; j < 4; ++j) {
                            uint32_t ad = AhB + (uint32_t)(((r0 + rt*16 + rsel)*CBP + 16*j + kh) * 2);
                            ldsm4(a[rt][j], ad);
                        }
                }
                int noff = (lane & 7) + ((lane >> 4) << 3);
                int kadd = ((lane >> 3) & 1) << 3;
                int rsub = lane >> 2;
                float best_lo[2] = {1e30f, 1e30f}, best_hi[2] = {1e30f, 1e30f};

                for (int chunk = 0; chunk < 8; ++chunk) {
                    float C[2][8][4];
                    #pragma unroll
                    for (int rt = 0; rt < 2; ++rt)
                        #pragma unroll
                        for (int t = 0; t < 8; ++t)
                            { C[rt][t][0]=0.f; C[rt][t][1]=0.f; C[rt][t][2]=0.f; C[rt][t][3]=0.f; }

                    #pragma unroll
                    for (int j = 0; j < 4; ++j) {
                        #pragma unroll
                        for (int tp = 0; tp < 4; ++tp) {
                            int n0 = chunk*64 + tp*16;
                            uint32_t bad = BhB + (uint32_t)(((n0 + noff)*CBP + 16*j + kadd) * 2);
                            uint32_t b[4];
                            ldsm4(b, bad);
                            #pragma unroll
                            for (int rt = 0; rt < 2; ++rt) {
                                mma16816(C[rt][2*tp],   a[rt][j], b[0], b[1]);
                                mma16816(C[rt][2*tp+1], a[rt][j], b[2], b[3]);
                            }
                        }
                    }

                    int code0base = chunk*64 + 2*(lane & 3);
                    #pragma unroll
                    for (int rt = 0; rt < 2; ++rt) {
                        #pragma unroll
                        for (int t = 0; t < 8; ++t) {
                            int c0 = code0base + t*8;
                            float cc0 = CC[c0], cc1 = CC[c0+1];
                            C[rt][t][0] = fmaf(-2.f, C[rt][t][0], cc0);
                            C[rt][t][1] = fmaf(-2.f, C[rt][t][1], cc1);
                            C[rt][t][2] = fmaf(-2.f, C[rt][t][2], cc0);
                            C[rt][t][3] = fmaf(-2.f, C[rt][t][3], cc1);
                            best_lo[rt] = fminf(best_lo[rt], fminf(C[rt][t][0], C[rt][t][1]));
                            best_hi[rt] = fminf(best_hi[rt], fminf(C[rt][t][2], C[rt][t][3]));
                        }
                        best_lo[rt] = fminf(best_lo[rt], __shfl_xor_sync(0xffffffffu, best_lo[rt], 1));
                        best_lo[rt] = fminf(best_lo[rt], __shfl_xor_sync(0xffffffffu, best_lo[rt], 2));
                        best_hi[rt] = fminf(best_hi[rt], __shfl_xor_sync(0xffffffffu, best_hi[rt], 1));
                        best_hi[rt] = fminf(best_hi[rt], __shfl_xor_sync(0xffffffffu, best_hi[rt], 2));
                        float thr_lo = best_lo[rt] + MARGIN, thr_hi = best_hi[rt] + MARGIN;
                        int row_lo = r0 + rt*16 + rsub, row_hi = row_lo + 8;

                        #pragma unroll
                        for (int t = 0; t < 8; ++t) {
                            int c0 = code0base + t*8;
                            if (C[rt][t][0] <= thr_lo) { int p = atomicAdd(&CNT[row_lo], 1); if (p < CAP) LIST[row_lo*CAP + p] = c0;   }
                            if (C[rt][t][1] <= thr_lo) { int p = atomicAdd(&CNT[row_lo], 1); if (p < CAP) LIST[row_lo*CAP + p] = c0+1; }
                            if (C[rt][t][2] <= thr_hi) { int p = atomicAdd(&CNT[row_hi], 1); if (p < CAP) LIST[row_hi*CAP + p] = c0;   }
                            if (C[rt][t][3] <= thr_hi) { int p = atomicAdd(&CNT[row_hi], 1); if (p < CAP) LIST[row_hi*CAP + p] = c0+1; }
                        }
                    }
                }
            }
            __syncwarp();   // warp's own LIST/CNT visible to its lanes

            // ---- exact fp32 rescore (warp-private: lane = row offset) ----
            {
                int r = r0 + lane;
                int n = tile*TILE_M + r;
                int cn = CNT[r];
                int bk;

                if (cn == 1) {
                    // candidate set provably contains the argmin; singleton = answer
                    bk = LIST[r*CAP];
                } else {
                    bool ovf = (cn > CAP) || (cn == 0);
                    if (cn > CAP) cn = CAP;

                    float invx = RV[cur*256 + r];
                    const float* xb = x + (size_t)(n >> 12)*CHW + (n & 4095);
                    float v[CDIM];
                    #pragma unroll
                    for (int c = 0; c < CDIM; ++c) v[c] = xb[(size_t)c*HW] * invx;

                    float bd = 1e30f;
                    bk = 0x7fffffff;

                    if (!ovf) {
                        for (int i = 0; i < cn; ++i) {
                            int k = LIST[r*CAP + i];
                            float invk = IV[k];
                            const float4* cb4 = (const float4*)(cb + (size_t)k*CDIM);
                            float d0 = 0.f, d1 = 0.f;
                            #pragma unroll
                            for (int q = 0; q < 16; q += 2) {
                                float4 ca = cb4[q], cb2 = cb4[q+1];
                                d0 = fmaf(v[4*q+0], ca.x*invk, d0);
                                d0 = fmaf(v[4*q+1], ca.y*invk, d0);
                                d0 = fmaf(v[4*q+2], ca.z*invk, d0);
                                d0 = fmaf(v[4*q+3], ca.w*invk, d0);
                                d1 = fmaf(v[4*q+4], cb2.x*invk, d1);
                                d1 = fmaf(v[4*q+5], cb2.y*invk, d1);
                                d1 = fmaf(v[4*q+6], cb2.z*invk, d1);
                                d1 = fmaf(v[4*q+7], cb2.w*invk, d1);
                            }
                            float d = fmaf(-2.f, d0 + d1, CC[k]);
                            if (d < bd || (d == bd && k < bk)) { bd = d; bk = k; }
                        }
                    } else {
                        for (int k = 0; k < KCODES; ++k) {
                            float invk = IV[k];
                            const float4* cb4 = (const float4*)(cb + (size_t)k*CDIM);
                            float d0 = 0.f;
                            #pragma unroll
                            for (int q = 0; q < 16; ++q) {
                                float4 ca = cb4[q];
                                d0 = fmaf(v[4*q+0], ca.x*invk, d0);
                                d0 = fmaf(v[4*q+1], ca.y*invk, d0);
                                d0 = fmaf(v[4*q+2], ca.z*invk, d0);
                                d0 = fmaf(v[4*q+3], ca.w*invk, d0);
                            }
                            float d = fmaf(-2.f, d0, CC[k]);
                            if (d < bd) { bd = d; bk = k; }   // ascending k: first-min
                        }
                    }
                }

                float invk = IV[bk];
                float* ob = out + (size_t)(n >> 12)*CHW + (n & 4095);
                const float4* cbb = (const float4*)(cb + (size_t)bk*CDIM);
                #pragma unroll
                for (int q = 0; q < 16; ++q) {
                    float4 vv = cbb[q];
                    int c = q * 4;
                    ob[(size_t)(c+0)*HW] = vv.x * invk;
                    ob[(size_t)(c+1)*HW] = vv.y * invk;
                    ob[(size_t)(c+2)*HW] = vv.z * invk;
                    ob[(size_t)(c+3)*HW] = vv.w * invk;
                }
                if (write_idx)
                    out[(size_t)NPIX*CDIM + n] = (float)bk;
            }
            BARALL();   // tile fully done; release A[cur] for refill
        }
        cur ^= 1;
    }
}

// ---------------------------------------------------------------------------
extern "C" void kernel_launch(void* const* d_in, const int* in_sizes, int n_in,
                              void* d_out, int out_size) {
    const float* x;
    const float* cb;
    if (in_sizes[0] == KCODES*CDIM) {
        cb = (const float*)d_in[0];
        x  = (const float*)d_in[1];
    } else {
        x  = (const float*)d_in[0];
        cb = (const float*)d_in[1];
    }
    float* out = (float*)d_out;

    cudaFuncSetAttribute(vq_kernel, cudaFuncAttributeMaxDynamicSharedMemorySize, SM_TOTAL);
    int write_idx = (out_size >= NPIX*CDIM + NPIX) ? 1 : 0;
    vq_kernel<<<GRID, THREADS, SM_TOTAL>>>(x, cb, out, write_idx);
}

// round 17
// speedup vs baseline: 1.6735x; 1.1142x over previous
#include <cuda_runtime.h>
#include <cuda_fp16.h>
#include <math.h>
#include <stdint.h>

#define KCODES 512
#define CDIM   64
#define NPIX   131072
#define HW     4096
#define CHW    262144
#define TILE_M 256
#define NT     (NPIX/TILE_M)    // 512 tiles
#define GRID   148              // persistent, 1 CTA/SM
#define THREADS 384             // 8 consumer warps + 4 producer warps
#define NCONS  256
#define CBP    72               // fp16 row pad (144B, conflict-free ldmatrix)
#define CAP    16
#define MARGIN 4e-3f

// ---------------- smem layout (188416 B, 1 CTA/SM) ----------------
#define OFF_B    0                 // 512*72*2 = 73728
#define OFF_A0   73728             // 256*72*2 = 36864
#define OFF_A1   110592            // 36864
#define OFF_CC   147456            // 2048
#define OFF_IV   149504            // 2048
#define OFF_RINV 151552            // 2*256*4 = 2048
#define OFF_LIST 153600            // 2*256*16*4 = 32768
#define OFF_CNT  186368            // 2*256*4 = 2048
#define SM_TOTAL 188416

// ---------------- helpers ----------------
__device__ __forceinline__ uint32_t smem_u32(const void* p) {
    uint32_t a;
    asm("{ .reg .u64 t; cvta.to.shared.u64 t, %1; cvt.u32.u64 %0, t; }" : "=r"(a) : "l"(p));
    return a;
}
__device__ __forceinline__ void ldsm4(uint32_t* r, uint32_t addr) {
    asm volatile("ldmatrix.sync.aligned.m8n8.x4.shared.b16 {%0,%1,%2,%3}, [%4];"
                 : "=r"(r[0]), "=r"(r[1]), "=r"(r[2]), "=r"(r[3]) : "r"(addr));
}
__device__ __forceinline__ void mma16816(float* c, const uint32_t* a,
                                         uint32_t b0, uint32_t b1) {
    asm volatile("mma.sync.aligned.m16n8k16.row.col.f32.f16.f16.f32 "
                 "{%0,%1,%2,%3}, {%4,%5,%6,%7}, {%8,%9}, {%0,%1,%2,%3};"
                 : "+f"(c[0]), "+f"(c[1]), "+f"(c[2]), "+f"(c[3])
                 : "r"(a[0]), "r"(a[1]), "r"(a[2]), "r"(a[3]), "r"(b0), "r"(b1));
}
#define BARALL()  asm volatile("bar.sync 1, 384;" ::: "memory")
#define BARPROD() asm volatile("bar.sync 3, 128;" ::: "memory")

// ---------------------------------------------------------------------------
// Warp-specialized persistent kernel, v2 pipeline:
//   consumers (warps 0-7): pure prune-GEMM on tile t  -> LIST[cur]
//   producers (warps 8-11): rescore+output tile t-1 (LIST[cur^1]),
//                           then fill A[cur^1] for tile t+1
// Arithmetic identical to the R16 champion; only work placement changed.
// ---------------------------------------------------------------------------
__global__ void __launch_bounds__(THREADS, 1)
vq_kernel(const float* __restrict__ x, const float* __restrict__ cb,
          float* __restrict__ out, int write_idx) {
    extern __shared__ char sm[];
    __half* Bh = (__half*)(sm + OFF_B);
    float*  CC = (float*)(sm + OFF_CC);
    float*  IV = (float*)(sm + OFF_IV);
    float*  RV = (float*)(sm + OFF_RINV);   // per-row x inv norm, 2 buffers
    int*  LIST = (int*)(sm + OFF_LIST);     // 2 buffers of 256*CAP
    int*   CNT = (int*)(sm + OFF_CNT);      // 2 buffers of 256

    int tid = threadIdx.x, lane = tid & 31, wid = tid >> 5;
    uint32_t smb = smem_u32(sm);
    uint32_t BhB = smb + OFF_B;
    uint32_t Aoff[2] = { smb + OFF_A0, smb + OFF_A1 };
    __half* Aptr[2] = { (__half*)(sm + OFF_A0), (__half*)(sm + OFF_A1) };

    // ---- init (all 384 threads): normalize codebook -> smem fp16 B + CC + IV
    for (int k = tid; k < KCODES; k += THREADS) {
        const float4* r4 = (const float4*)(cb + (size_t)k*CDIM);
        float4 buf[16];
        float ss = 0.f;
        #pragma unroll
        for (int q = 0; q < 16; ++q) {
            buf[q] = r4[q];
            ss += buf[q].x*buf[q].x; ss += buf[q].y*buf[q].y;
            ss += buf[q].z*buf[q].z; ss += buf[q].w*buf[q].w;
        }
        float inv = 1.0f / fmaxf(sqrtf(ss), 1e-12f);
        float cc = 0.f;
        #pragma unroll
        for (int q = 0; q < 16; ++q) {
            float v0 = buf[q].x*inv, v1 = buf[q].y*inv;
            float v2 = buf[q].z*inv, v3 = buf[q].w*inv;
            cc += v0*v0; cc += v1*v1; cc += v2*v2; cc += v3*v3;
            *(__half2*)(Bh + k*CBP + q*4)     = __floats2half2_rn(v0, v1);
            *(__half2*)(Bh + k*CBP + q*4 + 2) = __floats2half2_rn(v2, v3);
        }
        CC[k] = cc;
        IV[k] = inv;
    }
    __syncthreads();

    bool producer = (tid >= NCONS);
    int cur = 0;

    // ---- prologue: producers fill A[0]/RV[0] for first tile ----
    if (producer) {
        int pid = tid - NCONS;
        #pragma unroll
        for (int rep = 0; rep < 2; ++rep) {
            int r = pid + rep*128;
            int n = blockIdx.x*TILE_M + r;
            const float* xb = x + (size_t)(n >> 12)*CHW + (n & 4095);
            float v[CDIM];
            float ss = 0.f;
            #pragma unroll
            for (int c = 0; c < CDIM; ++c) { v[c] = xb[(size_t)c*HW]; ss += v[c]*v[c]; }
            float inv = 1.0f / fmaxf(sqrtf(ss), 1e-12f);
            #pragma unroll
            for (int i = 0; i < 32; ++i)
                *(__half2*)(Aptr[0] + r*CBP + 2*i) =
                    __floats2half2_rn(v[2*i]*inv, v[2*i+1]*inv);
            RV[r] = inv;   // buffer 0
        }
    }
    BARALL();   // A[0] ready

    int last_tile = -1, last_buf = 0;

    for (int tile = blockIdx.x; tile < NT; tile += GRID) {
        if (producer) {
            int pid = tid - NCONS;
            int pb = cur ^ 1;

            // ---- (a) rescore + output tile-GRID from LIST[pb]/RV[pb] ----
            if (tile - GRID >= 0) {
                int tprev = tile - GRID;
                #pragma unroll
                for (int rep = 0; rep < 2; ++rep) {
                    int r = pid + rep*128;
                    int n = tprev*TILE_M + r;
                    int cn = CNT[pb*256 + r];
                    int bk;
                    if (cn == 1) {
                        bk = LIST[pb*4096 + r*CAP];
                    } else {
                        bool ovf = (cn > CAP) || (cn == 0);
                        if (cn > CAP) cn = CAP;
                        float invx = RV[pb*256 + r];
                        const float* xb = x + (size_t)(n >> 12)*CHW + (n & 4095);
                        float v[CDIM];
                        #pragma unroll
                        for (int c = 0; c < CDIM; ++c) v[c] = xb[(size_t)c*HW] * invx;
                        float bd = 1e30f;
                        bk = 0x7fffffff;
                        if (!ovf) {
                            for (int i = 0; i < cn; ++i) {
                                int k = LIST[pb*4096 + r*CAP + i];
                                float invk = IV[k];
                                const float4* cb4 = (const float4*)(cb + (size_t)k*CDIM);
                                float d0 = 0.f, d1 = 0.f;
                                #pragma unroll
                                for (int q = 0; q < 16; q += 2) {
                                    float4 ca = cb4[q], cb2 = cb4[q+1];
                                    d0 = fmaf(v[4*q+0], ca.x*invk, d0);
                                    d0 = fmaf(v[4*q+1], ca.y*invk, d0);
                                    d0 = fmaf(v[4*q+2], ca.z*invk, d0);
                                    d0 = fmaf(v[4*q+3], ca.w*invk, d0);
                                    d1 = fmaf(v[4*q+4], cb2.x*invk, d1);
                                    d1 = fmaf(v[4*q+5], cb2.y*invk, d1);
                                    d1 = fmaf(v[4*q+6], cb2.z*invk, d1);
                                    d1 = fmaf(v[4*q+7], cb2.w*invk, d1);
                                }
                                float d = fmaf(-2.f, d0 + d1, CC[k]);
                                if (d < bd || (d == bd && k < bk)) { bd = d; bk = k; }
                            }
                        } else {
                            for (int k = 0; k < KCODES; ++k) {
                                float invk = IV[k];
                                const float4* cb4 = (const float4*)(cb + (size_t)k*CDIM);
                                float d0 = 0.f;
                                #pragma unroll
                                for (int q = 0; q < 16; ++q) {
                                    float4 ca = cb4[q];
                                    d0 = fmaf(v[4*q+0], ca.x*invk, d0);
                                    d0 = fmaf(v[4*q+1], ca.y*invk, d0);
                                    d0 = fmaf(v[4*q+2], ca.z*invk, d0);
                                    d0 = fmaf(v[4*q+3], ca.w*invk, d0);
                                }
                                float d = fmaf(-2.f, d0, CC[k]);
                                if (d < bd) { bd = d; bk = k; }   // first-min
                            }
                        }
                    }
                    float invk = IV[bk];
                    float* ob = out + (size_t)(n >> 12)*CHW + (n & 4095);
                    const float4* cbb = (const float4*)(cb + (size_t)bk*CDIM);
                    #pragma unroll
                    for (int q = 0; q < 16; ++q) {
                        float4 vv = cbb[q];
                        int c = q * 4;
                        ob[(size_t)(c+0)*HW] = vv.x * invk;
                        ob[(size_t)(c+1)*HW] = vv.y * invk;
                        ob[(size_t)(c+2)*HW] = vv.z * invk;
                        ob[(size_t)(c+3)*HW] = vv.w * invk;
                    }
                    if (write_idx)
                        out[(size_t)NPIX*CDIM + n] = (float)bk;
                }
            }
            BARPROD();   // RV[pb] reads done before overwrite below

            // ---- (b) fill A[pb]/RV[pb] for tile+GRID ----
            int nxt = tile + GRID;
            if (nxt < NT) {
                #pragma unroll
                for (int rep = 0; rep < 2; ++rep) {
                    int r = pid + rep*128;
                    int n = nxt*TILE_M + r;
                    const float* xb = x + (size_t)(n >> 12)*CHW + (n & 4095);
                    float v[CDIM];
                    float ss = 0.f;
                    #pragma unroll
                    for (int c = 0; c < CDIM; ++c) { v[c] = xb[(size_t)c*HW]; ss += v[c]*v[c]; }
                    float inv = 1.0f / fmaxf(sqrtf(ss), 1e-12f);
                    #pragma unroll
                    for (int i = 0; i < 32; ++i)
                        *(__half2*)(Aptr[pb] + r*CBP + 2*i) =
                            __floats2half2_rn(v[2*i]*inv, v[2*i+1]*inv);
                    RV[pb*256 + r] = inv;
                }
            }
            BARALL();   // rendezvous with consumers
        } else {
            // ---- consumers: pure prune-GEMM on A[cur] -> LIST[cur] ----
            int r0 = wid * 32;
            CNT[cur*256 + r0 + lane] = 0;   // warp-private rows
            __syncwarp();
            {
                uint32_t AhB = Aoff[cur];
                uint32_t a[2][4][4];
                {
                    int rsel = lane & 15, kh = (lane >> 4) << 3;
                    #pragma unroll
                    for (int rt = 0; rt < 2; ++rt)
                        #pragma unroll
                        for (int j = 0; j < 4; ++j) {
                            uint32_t ad = AhB + (uint32_t)(((r0 + rt*16 + rsel)*CBP + 16*j + kh) * 2);
                            ldsm4(a[rt][j], ad);
                        }
                }
                int noff = (lane & 7) + ((lane >> 4) << 3);
                int kadd = ((lane >> 3) & 1) << 3;
                int rsub = lane >> 2;
                float best_lo[2] = {1e30f, 1e30f}, best_hi[2] = {1e30f, 1e30f};

                for (int chunk = 0; chunk < 8; ++chunk) {
                    float C[2][8][4];
                    #pragma unroll
                    for (int rt = 0; rt < 2; ++rt)
                        #pragma unroll
                        for (int t = 0; t < 8; ++t)
                            { C[rt][t][0]=0.f; C[rt][t][1]=0.f; C[rt][t][2]=0.f; C[rt][t][3]=0.f; }

                    #pragma unroll
                    for (int j = 0; j < 4; ++j) {
                        #pragma unroll
                        for (int tp = 0; tp < 4; ++tp) {
                            int n0 = chunk*64 + tp*16;
                            uint32_t bad = BhB + (uint32_t)(((n0 + noff)*CBP + 16*j + kadd) * 2);
                            uint32_t b[4];
                            ldsm4(b, bad);
                            #pragma unroll
                            for (int rt = 0; rt < 2; ++rt) {
                                mma16816(C[rt][2*tp],   a[rt][j], b[0], b[1]);
                                mma16816(C[rt][2*tp+1], a[rt][j], b[2], b[3]);
                            }
                        }
                    }

                    int code0base = chunk*64 + 2*(lane & 3);
                    #pragma unroll
                    for (int rt = 0; rt < 2; ++rt) {
                        #pragma unroll
                        for (int t = 0; t < 8; ++t) {
                            int c0 = code0base + t*8;
                            float cc0 = CC[c0], cc1 = CC[c0+1];
                            C[rt][t][0] = fmaf(-2.f, C[rt][t][0], cc0);
                            C[rt][t][1] = fmaf(-2.f, C[rt][t][1], cc1);
                            C[rt][t][2] = fmaf(-2.f, C[rt][t][2], cc0);
                            C[rt][t][3] = fmaf(-2.f, C[rt][t][3], cc1);
                            best_lo[rt] = fminf(best_lo[rt], fminf(C[rt][t][0], C[rt][t][1]));
                            best_hi[rt] = fminf(best_hi[rt], fminf(C[rt][t][2], C[rt][t][3]));
                        }
                        best_lo[rt] = fminf(best_lo[rt], __shfl_xor_sync(0xffffffffu, best_lo[rt], 1));
                        best_lo[rt] = fminf(best_lo[rt], __shfl_xor_sync(0xffffffffu, best_lo[rt], 2));
                        best_hi[rt] = fminf(best_hi[rt], __shfl_xor_sync(0xffffffffu, best_hi[rt], 1));
                        best_hi[rt] = fminf(best_hi[rt], __shfl_xor_sync(0xffffffffu, best_hi[rt], 2));
                        float thr_lo = best_lo[rt] + MARGIN, thr_hi = best_hi[rt] + MARGIN;
                        int row_lo = r0 + rt*16 + rsub, row_hi = row_lo + 8;
                        int* cntb  = CNT + cur*256;
                        int* listb = LIST + cur*4096;

                        #pragma unroll
                        for (int t = 0; t < 8; ++t) {
                            int c0 = code0base + t*8;
                            if (C[rt][t][0] <= thr_lo) { int p = atomicAdd(&cntb[row_lo], 1); if (p < CAP) listb[row_lo*CAP + p] = c0;   }
                            if (C[rt][t][1] <= thr_lo) { int p = atomicAdd(&cntb[row_lo], 1); if (p < CAP) listb[row_lo*CAP + p] = c0+1; }
                            if (C[rt][t][2] <= thr_hi) { int p = atomicAdd(&cntb[row_hi], 1); if (p < CAP) listb[row_hi*CAP + p] = c0;   }
                            if (C[rt][t][3] <= thr_hi) { int p = atomicAdd(&cntb[row_hi], 1); if (p < CAP) listb[row_hi*CAP + p] = c0+1; }
                        }
                    }
                }
            }
            BARALL();   // publish LIST[cur] to producers; get A[cur^1]
        }
        last_tile = tile;
        last_buf  = cur;
        cur ^= 1;
    }

    // ---- epilogue: producers rescore + output the final tile ----
    if (producer && last_tile >= 0) {
        int pid = tid - NCONS;
        int pb = last_buf;
        #pragma unroll
        for (int rep = 0; rep < 2; ++rep) {
            int r = pid + rep*128;
            int n = last_tile*TILE_M + r;
            int cn = CNT[pb*256 + r];
            int bk;
            if (cn == 1) {
                bk = LIST[pb*4096 + r*CAP];
            } else {
                bool ovf = (cn > CAP) || (cn == 0);
                if (cn > CAP) cn = CAP;
                float invx = RV[pb*256 + r];
                const float* xb = x + (size_t)(n >> 12)*CHW + (n & 4095);
                float v[CDIM];
                #pragma unroll
                for (int c = 0; c < CDIM; ++c) v[c] = xb[(size_t)c*HW] * invx;
                float bd = 1e30f;
                bk = 0x7fffffff;
                if (!ovf) {
                    for (int i = 0; i < cn; ++i) {
                        int k = LIST[pb*4096 + r*CAP + i];
                        float invk = IV[k];
                        const float4* cb4 = (const float4*)(cb + (size_t)k*CDIM);
                        float d0 = 0.f, d1 = 0.f;
                        #pragma unroll
                        for (int q = 0; q < 16; q += 2) {
                            float4 ca = cb4[q], cb2 = cb4[q+1];
                            d0 = fmaf(v[4*q+0], ca.x*invk, d0);
                            d0 = fmaf(v[4*q+1], ca.y*invk, d0);
                            d0 = fmaf(v[4*q+2], ca.z*invk, d0);
                            d0 = fmaf(v[4*q+3], ca.w*invk, d0);
                            d1 = fmaf(v[4*q+4], cb2.x*invk, d1);
                            d1 = fmaf(v[4*q+5], cb2.y*invk, d1);
                            d1 = fmaf(v[4*q+6], cb2.z*invk, d1);
                            d1 = fmaf(v[4*q+7], cb2.w*invk, d1);
                        }
                        float d = fmaf(-2.f, d0 + d1, CC[k]);
                        if (d < bd || (d == bd && k < bk)) { bd = d; bk = k; }
                    }
                } else {
                    for (int k = 0; k < KCODES; ++k) {
                        float invk = IV[k];
                        const float4* cb4 = (const float4*)(cb + (size_t)k*CDIM);
                        float d0 = 0.f;
                        #pragma unroll
                        for (int q = 0; q < 16; ++q) {
                            float4 ca = cb4[q];
                            d0 = fmaf(v[4*q+0], ca.x*invk, d0);
                            d0 = fmaf(v[4*q+1], ca.y*invk, d0);
                            d0 = fmaf(v[4*q+2], ca.z*invk, d0);
                            d0 = fmaf(v[4*q+3], ca.w*invk, d0);
                        }
                        float d = fmaf(-2.f, d0, CC[k]);
                        if (d < bd) { bd = d; bk = k; }
                    }
                }
            }
            float invk = IV[bk];
            float* ob = out + (size_t)(n >> 12)*CHW + (n & 4095);
            const float4* cbb = (const float4*)(cb + (size_t)bk*CDIM);
            #pragma unroll
            for (int q = 0; q < 16; ++q) {
                float4 vv = cbb[q];
                int c = q * 4;
                ob[(size_t)(c+0)*HW] = vv.x * invk;
                ob[(size_t)(c+1)*HW] = vv.y * invk;
                ob[(size_t)(c+2)*HW] = vv.z * invk;
                ob[(size_t)(c+3)*HW] = vv.w * invk;
            }
            if (write_idx)
                out[(size_t)NPIX*CDIM + n] = (float)bk;
        }
    }
}

// ---------------------------------------------------------------------------
extern "C" void kernel_launch(void* const* d_in, const int* in_sizes, int n_in,
                              void* d_out, int out_size) {
    const float* x;
    const float* cb;
    if (in_sizes[0] == KCODES*CDIM) {
        cb = (const float*)d_in[0];
        x  = (const float*)d_in[1];
    } else {
        x  = (const float*)d_in[0];
        cb = (const float*)d_in[1];
    }
    float* out = (float*)d_out;

    cudaFuncSetAttribute(vq_kernel, cudaFuncAttributeMaxDynamicSharedMemorySize, SM_TOTAL);
    int write_idx = (out_size >= NPIX*CDIM + NPIX) ? 1 : 0;
    vq_kernel<<<GRID, THREADS, SM_TOTAL>>>(x, cb, out, write_idx);
}